// round 10
// baseline (speedup 1.0000x reference)
#include <cuda_runtime.h>
#include <cstdint>

// Row gather: out[row][:] = table[idx[row]][:], row in [0, 212992), row = 128B.
// R4 shape (proven optimal in sweep: 256 thr, 32 rows/warp) but with 256-bit
// LDG.E.256 / STG.E.256 (sm_103a): 4 lanes per row x 32B. Halves the gather +
// store instruction count and L1tex wavefront pressure vs float4.

static constexpr int  EMB_DIM        = 32;
static constexpr long NROWS          = 4096L * 26L * 2L;   // 212992
static constexpr int  THREADS        = 256;
static constexpr int  FLOATS_PER_ROW = EMB_DIM;            // 32 fp32 = 128B
static constexpr int  ROWS_PER_WARP  = 32;
static constexpr int  WARPS_PER_BLOCK= THREADS / 32;       // 8
static constexpr int  ROWS_PER_BLOCK = WARPS_PER_BLOCK * ROWS_PER_WARP;  // 256
static constexpr int  BLOCKS         = (int)(NROWS / ROWS_PER_BLOCK);    // 832
static constexpr int  STEPS          = 4;                  // 8 rows per step

struct v8 { float x0,x1,x2,x3,x4,x5,x6,x7; };

__device__ __forceinline__ v8 ldg256(const float* p) {
    v8 r;
    asm volatile("ld.global.nc.v8.f32 {%0,%1,%2,%3,%4,%5,%6,%7}, [%8];"
                 : "=f"(r.x0), "=f"(r.x1), "=f"(r.x2), "=f"(r.x3),
                   "=f"(r.x4), "=f"(r.x5), "=f"(r.x6), "=f"(r.x7)
                 : "l"(p));
    return r;
}

__device__ __forceinline__ void stg256_cs(float* p, const v8& v) {
    asm volatile("st.global.cs.v8.f32 [%0], {%1,%2,%3,%4,%5,%6,%7,%8};"
                 :: "l"(p),
                    "f"(v.x0), "f"(v.x1), "f"(v.x2), "f"(v.x3),
                    "f"(v.x4), "f"(v.x5), "f"(v.x6), "f"(v.x7)
                 : "memory");
}

__global__ __launch_bounds__(THREADS)
void gather_rows_kernel(const void*  __restrict__ idx_raw,
                        const float* __restrict__ table,
                        float*       __restrict__ out)
{
    const int lane = threadIdx.x & 31;
    const int warp = threadIdx.x >> 5;

    // ---- per-warp dtype probe: high words of the first 32 8-byte pairs ----
    unsigned int hiw = ((const unsigned int*)idx_raw)[2 * lane + 1];
    const bool is32 = __any_sync(0xffffffffu, hiw != 0);

    const long rowBase = ((long)blockIdx.x * WARPS_PER_BLOCK + warp) * ROWS_PER_WARP;

    // ---- one coalesced index load: lane L carries row rowBase+L ----
    long long myIdx;
    if (is32) myIdx = (long long)__ldg(((const int*)idx_raw) + rowBase + lane);
    else      myIdx = __ldg(((const long long*)idx_raw) + rowBase + lane);

    const int subrow = lane >> 2;   // 0..7: row within an 8-row step
    const int col    = lane & 3;    // which 32B chunk of the 128B row

    // ---- distribute indices: step s covers rows rowBase + s*8 .. +7 ----
    long r[STEPS];
#pragma unroll
    for (int s = 0; s < STEPS; s++)
        r[s] = (long)__shfl_sync(0xffffffffu, myIdx, s * 8 + subrow);

    // ---- 4 independent 256-bit gathers (same bytes in flight as 8x float4) ----
    v8 v[STEPS];
#pragma unroll
    for (int s = 0; s < STEPS; s++)
        v[s] = ldg256(table + r[s] * FLOATS_PER_ROW + col * 8);

    // ---- 4 coalesced 256-bit streaming stores (1KB contiguous per warp/step) ----
#pragma unroll
    for (int s = 0; s < STEPS; s++)
        stg256_cs(out + (rowBase + s * 8 + subrow) * FLOATS_PER_ROW + col * 8, v[s]);
}

extern "C" void kernel_launch(void* const* d_in, const int* in_sizes, int n_in,
                              void* d_out, int out_size)
{
    // Pick the index tensor by element count (212992 vs 32,000,000).
    const void*  idx;
    const float* table;
    if (in_sizes[0] == (int)NROWS) {
        idx   = d_in[0];
        table = (const float*)d_in[1];
    } else {
        idx   = d_in[1];
        table = (const float*)d_in[0];
    }

    gather_rows_kernel<<<BLOCKS, THREADS>>>(idx, table, (float*)d_out);
}

// round 11
// speedup vs baseline: 1.0029x; 1.0029x over previous
#include <cuda_runtime.h>
#include <cstdint>

// All2AllDenseEmbedding (gpu_num=1) == row gather:
//   out[row][:] = table[idx[row]][:], row in [0, 4096*26*2), row = 128B.
//
// FINAL (converged): across R4-R10 the warm-replay bench is pinned at
// 10.7-11.0us regardless of MLP (4-16), occupancy (31-73%), cache ops
// (__ldg/__ldcg, plain/.cs stores) and access width (128/256-bit) — the
// timed regime is bound by ~27MB DRAM output writes + L2-resident table
// reads + graph-replay overhead. This is the leanest member of the
// measured-best family: 256-thread blocks, 32 rows/warp, one coalesced
// index load per lane, shfl distribution, 8 independent float4 gathers
// per thread (MLP=8), 8 coalesced float4 stores. 832 blocks, exact tiling.

static constexpr int  EMB_DIM        = 32;
static constexpr long NROWS          = 4096L * 26L * 2L;   // 212992
static constexpr int  THREADS        = 256;
static constexpr int  VECS_PER_ROW   = EMB_DIM / 4;        // 8 float4 per row
static constexpr int  ROWS_PER_WARP  = 32;
static constexpr int  WARPS_PER_BLOCK= THREADS / 32;       // 8
static constexpr int  ROWS_PER_BLOCK = WARPS_PER_BLOCK * ROWS_PER_WARP;  // 256
static constexpr int  BLOCKS         = (int)(NROWS / ROWS_PER_BLOCK);    // 832, exact
static constexpr int  STEPS          = 8;                  // 4 rows per step

__global__ __launch_bounds__(THREADS)
void gather_rows_kernel(const void*   __restrict__ idx_raw,
                        const float4* __restrict__ table,
                        float4*       __restrict__ out)
{
    const int lane = threadIdx.x & 31;
    const int warp = threadIdx.x >> 5;

    // ---- per-warp dtype probe (int32 vs int64 indices): the high words of
    // the first 32 8-byte pairs are all zero iff the data is int64
    // (values < 2^20). Same 256B for every warp -> L1-hot after first touch.
    unsigned int hiw = ((const unsigned int*)idx_raw)[2 * lane + 1];
    const bool is32 = __any_sync(0xffffffffu, hiw != 0);

    const long rowBase = ((long)blockIdx.x * WARPS_PER_BLOCK + warp) * ROWS_PER_WARP;

    // ---- one coalesced index load: lane L carries row rowBase+L ----
    long long myIdx;
    if (is32) myIdx = (long long)__ldg(((const int*)idx_raw) + rowBase + lane);
    else      myIdx = __ldg(((const long long*)idx_raw) + rowBase + lane);

    const int subrow = lane >> 3;   // 0..3: row within a 4-row step
    const int col    = lane & 7;    // float4 slot within row

    // ---- distribute indices: step s covers rows rowBase + s*4 .. +3 ----
    long r[STEPS];
#pragma unroll
    for (int s = 0; s < STEPS; s++)
        r[s] = (long)__shfl_sync(0xffffffffu, myIdx, s * 4 + subrow);

    // ---- 8 independent gathers (MLP=8): each row = exactly one 128B line ----
    float4 v[STEPS];
#pragma unroll
    for (int s = 0; s < STEPS; s++)
        v[s] = __ldg(table + r[s] * VECS_PER_ROW + col);

    // ---- 8 coalesced stores (512B contiguous per warp per step) ----
#pragma unroll
    for (int s = 0; s < STEPS; s++)
        out[(rowBase + s * 4 + subrow) * VECS_PER_ROW + col] = v[s];
}

extern "C" void kernel_launch(void* const* d_in, const int* in_sizes, int n_in,
                              void* d_out, int out_size)
{
    // Pick the index tensor by element count (212992 vs 32,000,000).
    const void*  idx;
    const float* table;
    if (in_sizes[0] == (int)NROWS) {
        idx   = d_in[0];
        table = (const float*)d_in[1];
    } else {
        idx   = d_in[1];
        table = (const float*)d_in[0];
    }

    gather_rows_kernel<<<BLOCKS, THREADS>>>(idx, (const float4*)table, (float4*)d_out);
}